// round 3
// baseline (speedup 1.0000x reference)
#include <cuda_runtime.h>
#include <cuda_bf16.h>

// ROI-Align (Mask R-CNN multi-level crop_and_resize), POOL=7, C=256, N=1000.
// Layout: lane = pos*4 + corner  -> the 4 bilinear corners of one sample sit in
// adjacent lanes of the SAME LDG instruction, so x-adjacent corners share 32B
// sectors (L1 wavefront reduction). Offsets/weights live in registers; the
// channel loop is pure pointer-increment + LDG + FMUL + 2x shfl_xor + STG.

#define POOLP 49
#define CCH   256
#define NTHR  224   // 7 warps; lanes 0..195 active (49 pos * 4 corners)

__global__ __launch_bounds__(NTHR) void roialign_kernel(
    const float* __restrict__ boxes,
    const float* __restrict__ p2,
    const float* __restrict__ p3,
    const float* __restrict__ p4,
    const float* __restrict__ p5,
    float* __restrict__ out)
{
    const int n = blockIdx.x;
    const int s = threadIdx.x;
    const int corner = s & 3;
    const int pos    = s >> 2;          // 0..55
    const bool active = pos < POOLP;
    const int pp = active ? pos : 0;
    const int py = pp / 7;
    const int px = pp - py * 7;

    // Every thread redoes the (cheap) per-box math; boxes reads broadcast from L1.
    const float y1 = __ldg(boxes + n * 4 + 0);
    const float x1 = __ldg(boxes + n * 4 + 1);
    const float y2 = __ldg(boxes + n * 4 + 2);
    const float x2 = __ldg(boxes + n * 4 + 3);

    // roi_level = clip(round(4 + log2(sqrt(h*w) / (224/1024))), 2, 5); round = half-to-even.
    const float lvl_f = 4.0f + log2f(sqrtf((y2 - y1) * (x2 - x1)) / 0.21875f);
    int lvl = (int)rintf(lvl_f);
    lvl = lvl < 2 ? 2 : (lvl > 5 ? 5 : lvl);

    const float* fm;
    int H;
    if      (lvl == 2) { fm = p2; H = 256; }
    else if (lvl == 3) { fm = p3; H = 128; }
    else if (lvl == 4) { fm = p4; H = 64;  }
    else               { fm = p5; H = 32;  }
    const int W  = H;
    const int HW = H * W;

    // Sample coordinates (match jax f32 arithmetic: t = i / 6.0f as division).
    const float ty = (float)py / 6.0f;
    const float tx = (float)px / 6.0f;
    const float yy = (y1 + (y2 - y1) * ty) * (float)(H - 1);
    const float xx = (x1 + (x2 - x1) * tx) * (float)(W - 1);

    const float y0f = floorf(yy);
    const float x0f = floorf(xx);
    const float wy = yy - y0f;
    const float wx = xx - x0f;

    int iy0 = (int)y0f; iy0 = iy0 < 0 ? 0 : (iy0 > H - 1 ? H - 1 : iy0);
    int iy1 = (iy0 + 1 > H - 1) ? (H - 1) : (iy0 + 1);
    int ix0 = (int)x0f; ix0 = ix0 < 0 ? 0 : (ix0 > W - 1 ? W - 1 : ix0);
    int ix1 = (ix0 + 1 > W - 1) ? (W - 1) : (ix0 + 1);

    const bool inb = (yy >= 0.0f) && (yy <= (float)(H - 1)) &&
                     (xx >= 0.0f) && (xx <= (float)(W - 1));

    const int   iy = (corner & 2) ? iy1 : iy0;
    const int   ix = (corner & 1) ? ix1 : ix0;
    float wgt = ((corner & 2) ? wy : 1.0f - wy) *
                ((corner & 1) ? wx : 1.0f - wx);
    if (!inb || !active) wgt = 0.0f;

    const float* p  = fm + (iy * W + ix);
    float*       po = out + (size_t)n * (CCH * POOLP) + pp;
    const bool   do_store = active && (corner == 0);

    #pragma unroll 4
    for (int c = 0; c < CCH; ++c) {
        float v = wgt * __ldg(p);
        v += __shfl_xor_sync(0xFFFFFFFFu, v, 1);
        v += __shfl_xor_sync(0xFFFFFFFFu, v, 2);
        if (do_store) *po = v;
        p  += HW;
        po += POOLP;
    }
}

extern "C" void kernel_launch(void* const* d_in, const int* in_sizes, int n_in,
                              void* d_out, int out_size)
{
    const float* boxes = (const float*)d_in[0];
    const float* p2    = (const float*)d_in[1];
    const float* p3    = (const float*)d_in[2];
    const float* p4    = (const float*)d_in[3];
    const float* p5    = (const float*)d_in[4];
    float* out = (float*)d_out;

    roialign_kernel<<<1000, NTHR>>>(boxes, p2, p3, p4, p5, out);
}

// round 4
// speedup vs baseline: 1.1711x; 1.1711x over previous
#include <cuda_runtime.h>
#include <cuda_bf16.h>

// ROI-Align (Mask R-CNN multi-level crop_and_resize), POOL=7, C=256, N=1000.
// R4: fixed (pos -> thread) assignment; per-thread 4 corner offsets + 4 weights
// hoisted to registers. Inner loop over a 64-channel slice: 4 LDG + FMA chain +
// coalesced STG. No shared memory, no shuffles in the hot loop.

#define POOLP 49
#define CCH   256
#define NGRP  4                 // channel groups per box
#define CPG   (CCH / NGRP)      // 64 channels per thread
#define NTHR  (POOLP * NGRP)    // 196 threads

__global__ __launch_bounds__(NTHR) void roialign_kernel(
    const float* __restrict__ boxes,
    const float* __restrict__ p2,
    const float* __restrict__ p3,
    const float* __restrict__ p4,
    const float* __restrict__ p5,
    float* __restrict__ out)
{
    const int n = blockIdx.x;
    const int tid = threadIdx.x;
    const int pos = tid % POOLP;
    const int grp = tid / POOLP;        // 0..3
    const int py = pos / 7;
    const int px = pos - py * 7;

    // Per-box math redone by every thread (cheap; boxes reads broadcast).
    const float y1 = __ldg(boxes + n * 4 + 0);
    const float x1 = __ldg(boxes + n * 4 + 1);
    const float y2 = __ldg(boxes + n * 4 + 2);
    const float x2 = __ldg(boxes + n * 4 + 3);

    // roi_level = clip(round(4 + log2(sqrt(h*w) / (224/1024))), 2, 5); round half-to-even.
    const float lvl_f = 4.0f + log2f(sqrtf((y2 - y1) * (x2 - x1)) / 0.21875f);
    int lvl = (int)rintf(lvl_f);
    lvl = lvl < 2 ? 2 : (lvl > 5 ? 5 : lvl);

    const float* fm;
    int H;
    if      (lvl == 2) { fm = p2; H = 256; }
    else if (lvl == 3) { fm = p3; H = 128; }
    else if (lvl == 4) { fm = p4; H = 64;  }
    else               { fm = p5; H = 32;  }
    const int W  = H;
    const int HW = H * W;

    // Sample coordinates; match jax f32 arithmetic (t = i / 6.0f as division).
    const float ty = (float)py / 6.0f;
    const float tx = (float)px / 6.0f;
    const float yy = (y1 + (y2 - y1) * ty) * (float)(H - 1);
    const float xx = (x1 + (x2 - x1) * tx) * (float)(W - 1);

    const float y0f = floorf(yy);
    const float x0f = floorf(xx);
    const float wy = yy - y0f;
    const float wx = xx - x0f;

    int iy0 = (int)y0f; iy0 = iy0 < 0 ? 0 : (iy0 > H - 1 ? H - 1 : iy0);
    int iy1 = (iy0 + 1 > H - 1) ? (H - 1) : (iy0 + 1);
    int ix0 = (int)x0f; ix0 = ix0 < 0 ? 0 : (ix0 > W - 1 ? W - 1 : ix0);
    int ix1 = (ix0 + 1 > W - 1) ? (W - 1) : (ix0 + 1);

    const bool inb = (yy >= 0.0f) && (yy <= (float)(H - 1)) &&
                     (xx >= 0.0f) && (xx <= (float)(W - 1));
    const float m = inb ? 1.0f : 0.0f;

    // Register-resident offsets and weights for this thread's fixed pos.
    const int o00 = iy0 * W + ix0;
    const int o01 = iy0 * W + ix1;
    const int o10 = iy1 * W + ix0;
    const int o11 = iy1 * W + ix1;
    const float w00 = m * (1.0f - wy) * (1.0f - wx);
    const float w01 = m * (1.0f - wy) * wx;
    const float w10 = m * wy * (1.0f - wx);
    const float w11 = m * wy * wx;

    const float* __restrict__ b  = fm + (size_t)(grp * CPG) * HW;
    float*       __restrict__ po = out + (size_t)n * (CCH * POOLP)
                                       + (size_t)(grp * CPG) * POOLP + pos;

    #pragma unroll 4
    for (int c = 0; c < CPG; ++c) {
        float v = w00 * __ldg(b + o00)
                + w01 * __ldg(b + o01)
                + w10 * __ldg(b + o10)
                + w11 * __ldg(b + o11);
        *po = v;
        b  += HW;
        po += POOLP;
    }
}

extern "C" void kernel_launch(void* const* d_in, const int* in_sizes, int n_in,
                              void* d_out, int out_size)
{
    const float* boxes = (const float*)d_in[0];
    const float* p2    = (const float*)d_in[1];
    const float* p3    = (const float*)d_in[2];
    const float* p4    = (const float*)d_in[3];
    const float* p5    = (const float*)d_in[4];
    float* out = (float*)d_out;

    roialign_kernel<<<1000, NTHR>>>(boxes, p2, p3, p4, p5, out);
}